// round 3
// baseline (speedup 1.0000x reference)
#include <cuda_runtime.h>
#include <cstdint>

// Problem constants (fixed by the reference)
constexpr int Bc = 4, S = 2048, D = 2048, H = 16, DH = 128;
constexpr int M_ROWS = Bc * S;  // 8192

// Scratch (device globals: allocation in kernel_launch is forbidden)
__device__ float g_Q[(size_t)M_ROWS * D];
__device__ float g_K[(size_t)M_ROWS * D];
__device__ float g_V[(size_t)M_ROWS * D];
__device__ float g_A[(size_t)M_ROWS * D];

// ---------------- packed f32x2 helpers (Blackwell FFMA2 path) ----------------
__device__ __forceinline__ unsigned long long dup2(float x) {
    unsigned long long r;
    asm("mov.b64 %0, {%1, %1};" : "=l"(r) : "f"(x));
    return r;
}
__device__ __forceinline__ void fma2(unsigned long long& d, unsigned long long a,
                                     unsigned long long b) {
    asm("fma.rn.f32x2 %0, %1, %2, %0;" : "+l"(d) : "l"(a), "l"(b));
}
__device__ __forceinline__ void mul2(unsigned long long& d, unsigned long long a) {
    asm("mul.rn.f32x2 %0, %0, %1;" : "+l"(d) : "l"(a));
}
__device__ __forceinline__ float2 unpack2(unsigned long long v) {
    float2 f;
    asm("mov.b64 {%0, %1}, %2;" : "=f"(f.x), "=f"(f.y) : "l"(v));
    return f;
}
__device__ __forceinline__ float ex2(float x) {
    float y;
    asm("ex2.approx.ftz.f32 %0, %1;" : "=f"(y) : "f"(x));
    return y;
}

// ---------------------------------------------------------------------------
// SGEMM + bias: C[M,N] = A[M,K] @ W[K,N] + bias[N].  fp32, FFMA2.
// 128x128 tile, BK=8, 256 threads, 8x8 micro-tile/thread.
// Thread's 8 output columns are split {tx*4..+3, 64+tx*4..+3} so every smem
// B-read covers 64 contiguous floats across 16 lanes (conflict-free).
// Next k-tile is prefetched into registers while the current one computes.
// ---------------------------------------------------------------------------
__global__ __launch_bounds__(256, 2)
void sgemm_bias(const float* __restrict__ A, const float* __restrict__ W,
                const float* __restrict__ bias, float* __restrict__ C,
                int M, int N, int K) {
    constexpr int AP = 12;                 // As row pitch (floats)
    __shared__ float As[128 * AP];         // row-major [m][k]
    __shared__ float Bs[8 * 132];          // row-major [k][n]

    const int tid = threadIdx.x;
    const int tx = tid & 15;               // n micro index
    const int ty = tid >> 4;               // m micro index
    const int m0 = blockIdx.y * 128;
    const int n0 = blockIdx.x * 128;

    unsigned long long acc[8][4];
#pragma unroll
    for (int i = 0; i < 8; i++)
#pragma unroll
        for (int j = 0; j < 4; j++) acc[i][j] = 0ull;

    const int ar = tid >> 1, ac = (tid & 1) * 4;
    const int br = tid >> 5, bc = (tid & 31) * 4;
    const float* Ap = A + (size_t)(m0 + ar) * K + ac;
    const float* Wp = W + (size_t)br * N + n0 + bc;

    float4 av = *(const float4*)(Ap);
    float4 bv = *(const float4*)(Wp);

    for (int k0 = 0; k0 < K; k0 += 8) {
        *(float4*)&As[ar * AP + ac] = av;
        *(float4*)&Bs[br * 132 + bc] = bv;
        __syncthreads();
        if (k0 + 8 < K) {  // prefetch next k-tile (overlaps with compute)
            av = *(const float4*)(Ap + k0 + 8);
            bv = *(const float4*)(Wp + (size_t)(k0 + 8) * N);
        }
#pragma unroll
        for (int kk = 0; kk < 8; kk++) {
            ulonglong2 b0 = *(const ulonglong2*)&Bs[kk * 132 + tx * 4];
            ulonglong2 b1 = *(const ulonglong2*)&Bs[kk * 132 + 64 + tx * 4];
#pragma unroll
            for (int i = 0; i < 8; i++) {
                unsigned long long ad = dup2(As[(ty * 8 + i) * AP + kk]);
                fma2(acc[i][0], ad, b0.x);
                fma2(acc[i][1], ad, b0.y);
                fma2(acc[i][2], ad, b1.x);
                fma2(acc[i][3], ad, b1.y);
            }
        }
        __syncthreads();
    }

    float4 ba = *(const float4*)(bias + n0 + tx * 4);
    float4 bb = *(const float4*)(bias + n0 + 64 + tx * 4);
#pragma unroll
    for (int i = 0; i < 8; i++) {
        size_t row = (size_t)(m0 + ty * 8 + i);
        float* Cp = C + row * N + n0;
        float2 f0 = unpack2(acc[i][0]), f1 = unpack2(acc[i][1]);
        float2 f2 = unpack2(acc[i][2]), f3 = unpack2(acc[i][3]);
        *(float4*)(Cp + tx * 4) =
            make_float4(f0.x + ba.x, f0.y + ba.y, f1.x + ba.z, f1.y + ba.w);
        *(float4*)(Cp + 64 + tx * 4) =
            make_float4(f2.x + bb.x, f2.y + bb.y, f3.x + bb.z, f3.y + bb.w);
    }
}

// ---------------------------------------------------------------------------
// Fused attention faithful to the reference:
//   p = softmax over ALL keys (full-row denominator)
//   out[q] = sum_{k<=q} p[q,k] V[k]  - 1e9 * sum_{k>q} V[k]
// One CTA per (128 q-rows, head, batch). 256 threads, 8x8 micro-tile with the
// same split-column mapping {tx*4, 64+tx*4}. Diagonal key tile is processed
// LAST so its V tile stays resident in smem for the per-row suffix scan.
// Above-diagonal tiles contribute only to (m,l) and a V column-sum.
// ---------------------------------------------------------------------------
constexpr float SCALE_LOG2E = 0.08838834764831845f * 1.4426950408889634f;
constexpr int TP = 132;  // tile row pitch (floats)
constexpr size_t ATTN_SMEM = (size_t)(3 * 128 * TP + 256) * sizeof(float);

__global__ __launch_bounds__(256, 1)
void attn_kernel(const float* __restrict__ Q, const float* __restrict__ K,
                 const float* __restrict__ V, float* __restrict__ O) {
    extern __shared__ float sm[];
    float* Qs = sm;                     // Qs[q][d]  (pre-scaled by SCALE*log2e)
    float* B1 = sm + 128 * TP;          // Kt[d][k] during scores; P[q][k] after
    float* Vs = sm + 2 * 128 * TP;      // Vs[k][d]
    float* scr = sm + 3 * 128 * TP;     // 256 floats scratch (V colsum)

    const int tid = threadIdx.x;
    const int tx = tid & 15;
    const int ty = tid >> 4;
    const int qb = blockIdx.x;
    const int h = blockIdx.y;
    const int b = blockIdx.z;
    const int q0 = qb * 128;

    const float* Qg = Q + ((size_t)b * S + q0) * D + h * DH;
    const float* Kg = K + (size_t)b * S * D + h * DH;
    const float* Vg = V + (size_t)b * S * D + h * DH;

    // Load Q (row-major, pre-scaled). Coalesced; conflict-free stores.
    {
        const int lane = tid & 31;
#pragma unroll
        for (int it = 0; it < 16; it++) {
            int row = it * 8 + (tid >> 5);
            float4 v = *(const float4*)(Qg + (size_t)row * D + lane * 4);
            v.x *= SCALE_LOG2E; v.y *= SCALE_LOG2E;
            v.z *= SCALE_LOG2E; v.w *= SCALE_LOG2E;
            *(float4*)&Qs[row * TP + lane * 4] = v;
        }
    }

    unsigned long long acc[8][4];
#pragma unroll
    for (int i = 0; i < 8; i++)
#pragma unroll
        for (int j = 0; j < 4; j++) acc[i][j] = 0ull;
    float m_r[8], l_r[8];
#pragma unroll
    for (int i = 0; i < 8; i++) { m_r[i] = -1e30f; l_r[i] = 0.f; }

    float psum = 0.f;                 // far-tile V column-sum partial
    const int cd = tid & 127;         // owned column for colsum
    const int ck0 = (tid >> 7) * 64;  // k half-range

    constexpr int NT = S / 128;       // 16
    for (int t = 0; t < NT; t++) {
        const int j = (t < NT - 1) ? (t < qb ? t : t + 1) : qb;  // diagonal LAST

        // Load K transposed (Kt[d][k]) + V row-major (Vs[k][d]).
        {
            const int r2 = tid >> 1, c2 = (tid & 1) * 64;
            const float* Kr = Kg + (size_t)(j * 128 + r2) * D + c2;
            const float* Vr = Vg + (size_t)(j * 128 + r2) * D + c2;
#pragma unroll
            for (int f = 0; f < 16; f++) {
                float4 kv = *(const float4*)(Kr + f * 4);
                B1[(c2 + f * 4 + 0) * TP + r2] = kv.x;
                B1[(c2 + f * 4 + 1) * TP + r2] = kv.y;
                B1[(c2 + f * 4 + 2) * TP + r2] = kv.z;
                B1[(c2 + f * 4 + 3) * TP + r2] = kv.w;
                *(float4*)&Vs[r2 * TP + c2 + f * 4] = *(const float4*)(Vr + f * 4);
            }
        }
        __syncthreads();

        // Scores: s[q][k] = Qs[q][:] . Kt[:][k]   (log2-scaled domain)
        unsigned long long sacc[8][4];
#pragma unroll
        for (int i = 0; i < 8; i++)
#pragma unroll
            for (int jp = 0; jp < 4; jp++) sacc[i][jp] = 0ull;

        for (int d0 = 0; d0 < 128; d0 += 2) {
            float2 qv[8];
#pragma unroll
            for (int i = 0; i < 8; i++)
                qv[i] = *(const float2*)&Qs[(ty * 8 + i) * TP + d0];
#pragma unroll
            for (int dd = 0; dd < 2; dd++) {
                ulonglong2 b0 = *(const ulonglong2*)&B1[(d0 + dd) * TP + tx * 4];
                ulonglong2 b1 = *(const ulonglong2*)&B1[(d0 + dd) * TP + 64 + tx * 4];
#pragma unroll
                for (int i = 0; i < 8; i++) {
                    unsigned long long ad = dup2(dd ? qv[i].y : qv[i].x);
                    fma2(sacc[i][0], ad, b0.x);
                    fma2(sacc[i][1], ad, b0.y);
                    fma2(sacc[i][2], ad, b1.x);
                    fma2(sacc[i][3], ad, b1.y);
                }
            }
        }

        // Softmax update (full row: every tile contributes to m, l)
        float p[8][8];
#pragma unroll
        for (int i = 0; i < 8; i++) {
#pragma unroll
            for (int jp = 0; jp < 4; jp++) {
                float2 f = unpack2(sacc[i][jp]);
                p[i][2 * jp] = f.x;
                p[i][2 * jp + 1] = f.y;
            }
            float rm = p[i][0];
#pragma unroll
            for (int jj = 1; jj < 8; jj++) rm = fmaxf(rm, p[i][jj]);
            rm = fmaxf(rm, __shfl_xor_sync(0xffffffffu, rm, 1));
            rm = fmaxf(rm, __shfl_xor_sync(0xffffffffu, rm, 2));
            rm = fmaxf(rm, __shfl_xor_sync(0xffffffffu, rm, 4));
            rm = fmaxf(rm, __shfl_xor_sync(0xffffffffu, rm, 8));
            float mn = fmaxf(m_r[i], rm);
            float fac = ex2(m_r[i] - mn);
            m_r[i] = mn;
            float rs = 0.f;
#pragma unroll
            for (int jj = 0; jj < 8; jj++) {
                float e = ex2(p[i][jj] - mn);
                p[i][jj] = e;
                rs += e;
            }
            rs += __shfl_xor_sync(0xffffffffu, rs, 1);
            rs += __shfl_xor_sync(0xffffffffu, rs, 2);
            rs += __shfl_xor_sync(0xffffffffu, rs, 4);
            rs += __shfl_xor_sync(0xffffffffu, rs, 8);
            l_r[i] = l_r[i] * fac + rs;
            unsigned long long fd = dup2(fac);
#pragma unroll
            for (int jp = 0; jp < 4; jp++) mul2(acc[i][jp], fd);
        }

        if (j <= qb) {
            if (j == qb) {  // causal mask on the numerator only
#pragma unroll
                for (int i = 0; i < 8; i++)
#pragma unroll
                    for (int jj = 0; jj < 8; jj++) {
                        int col = (jj < 4) ? tx * 4 + jj : 64 + tx * 4 + jj - 4;
                        if (col > ty * 8 + i) p[i][jj] = 0.f;
                    }
            }
            __syncthreads();  // everyone done reading Kt before overwrite
#pragma unroll
            for (int i = 0; i < 8; i++) {
                *(float4*)&B1[(ty * 8 + i) * TP + tx * 4] =
                    make_float4(p[i][0], p[i][1], p[i][2], p[i][3]);
                *(float4*)&B1[(ty * 8 + i) * TP + 64 + tx * 4] =
                    make_float4(p[i][4], p[i][5], p[i][6], p[i][7]);
            }
            __syncthreads();
            // acc += P @ V
            for (int k0 = 0; k0 < 128; k0 += 2) {
                float2 pv[8];
#pragma unroll
                for (int i = 0; i < 8; i++)
                    pv[i] = *(const float2*)&B1[(ty * 8 + i) * TP + k0];
#pragma unroll
                for (int kk = 0; kk < 2; kk++) {
                    ulonglong2 b0 = *(const ulonglong2*)&Vs[(k0 + kk) * TP + tx * 4];
                    ulonglong2 b1 = *(const ulonglong2*)&Vs[(k0 + kk) * TP + 64 + tx * 4];
#pragma unroll
                    for (int i = 0; i < 8; i++) {
                        unsigned long long ad = dup2(kk ? pv[i].y : pv[i].x);
                        fma2(acc[i][0], ad, b0.x);
                        fma2(acc[i][1], ad, b0.y);
                        fma2(acc[i][2], ad, b1.x);
                        fma2(acc[i][3], ad, b1.y);
                    }
                }
            }
        } else {
            // Far-above-diagonal: only the V column-sum is needed (suffix term)
            for (int k = ck0; k < ck0 + 64; k++) psum += Vs[k * TP + cd];
        }
        __syncthreads();  // before next tile overwrites B1/Vs
    }

    // Combine the two k-half partials of the far-tile V column sums.
    scr[tid] = psum;
    __syncthreads();
    if (tid < 128) scr[tid] += scr[tid + 128];
    __syncthreads();

    // Epilogue. Vs still holds the DIAGONAL V tile (processed last).
    float inv_l[8];
#pragma unroll
    for (int i = 0; i < 8; i++) inv_l[i] = 1.f / l_r[i];
    float sfv[8];
#pragma unroll
    for (int jj = 0; jj < 8; jj++) {
        int col = (jj < 4) ? tx * 4 + jj : 64 + tx * 4 + jj - 4;
        sfv[jj] = scr[col];
    }

    const int qlo = ty * 8;
    float run[8];
#pragma unroll
    for (int jj = 0; jj < 8; jj++) run[jj] = 0.f;

    float* Obase = O + ((size_t)b * S + q0) * D + h * DH;
    int kk = 127;  // next diagonal-tile V row to fold into the suffix
#pragma unroll
    for (int i = 7; i >= 0; --i) {
        const int q = qlo + i;
        for (; kk > q; --kk) {
            float4 v0 = *(const float4*)&Vs[kk * TP + tx * 4];
            float4 v1 = *(const float4*)&Vs[kk * TP + 64 + tx * 4];
            run[0] += v0.x; run[1] += v0.y; run[2] += v0.z; run[3] += v0.w;
            run[4] += v1.x; run[5] += v1.y; run[6] += v1.z; run[7] += v1.w;
        }
        float o[8];
#pragma unroll
        for (int jp = 0; jp < 4; jp++) {
            float2 f = unpack2(acc[i][jp]);
            o[2 * jp] = f.x;
            o[2 * jp + 1] = f.y;
        }
#pragma unroll
        for (int jj = 0; jj < 8; jj++)
            o[jj] = o[jj] * inv_l[i] - 1e9f * (sfv[jj] + run[jj]);
        float* Op = Obase + (size_t)q * D;
        *(float4*)(Op + tx * 4) = make_float4(o[0], o[1], o[2], o[3]);
        *(float4*)(Op + 64 + tx * 4) = make_float4(o[4], o[5], o[6], o[7]);
    }
}

// ---------------------------------------------------------------------------
extern "C" void kernel_launch(void* const* d_in, const int* in_sizes, int n_in,
                              void* d_out, int out_size) {
    const float* q  = (const float*)d_in[0];
    const float* k  = (const float*)d_in[1];
    const float* v  = (const float*)d_in[2];
    const float* Wq = (const float*)d_in[3];
    const float* bq = (const float*)d_in[4];
    const float* Wk = (const float*)d_in[5];
    const float* bk = (const float*)d_in[6];
    const float* Wv = (const float*)d_in[7];
    const float* bv = (const float*)d_in[8];
    const float* Wo = (const float*)d_in[9];
    const float* bo = (const float*)d_in[10];
    float* out = (float*)d_out;

    float *Qb, *Kb, *Vb, *Ab;
    cudaGetSymbolAddress((void**)&Qb, g_Q);
    cudaGetSymbolAddress((void**)&Kb, g_K);
    cudaGetSymbolAddress((void**)&Vb, g_V);
    cudaGetSymbolAddress((void**)&Ab, g_A);

    cudaFuncSetAttribute(attn_kernel, cudaFuncAttributeMaxDynamicSharedMemorySize,
                         (int)ATTN_SMEM);

    dim3 gg(D / 128, M_ROWS / 128);  // (16, 64)
    sgemm_bias<<<gg, 256>>>(q, Wq, bq, Qb, M_ROWS, D, D);
    sgemm_bias<<<gg, 256>>>(k, Wk, bk, Kb, M_ROWS, D, D);
    sgemm_bias<<<gg, 256>>>(v, Wv, bv, Vb, M_ROWS, D, D);

    attn_kernel<<<dim3(S / 128, H, Bc), 256, ATTN_SMEM>>>(Qb, Kb, Vb, Ab);

    sgemm_bias<<<gg, 256>>>(Ab, Wo, bo, out, M_ROWS, D, D);
}

// round 4
// speedup vs baseline: 1.2406x; 1.2406x over previous
#include <cuda_runtime.h>
#include <cstdint>

// Problem constants (fixed by the reference)
constexpr int Bc = 4, S = 2048, D = 2048, H = 16, DH = 128;
constexpr int M_ROWS = Bc * S;  // 8192

// Scratch (device globals: allocation in kernel_launch is forbidden)
__device__ float g_Q[(size_t)M_ROWS * D];
__device__ float g_K[(size_t)M_ROWS * D];
__device__ float g_V[(size_t)M_ROWS * D];
__device__ float g_A[(size_t)M_ROWS * D];

// ---------------- packed f32x2 helpers (Blackwell FFMA2 path) ----------------
__device__ __forceinline__ unsigned long long dup2(float x) {
    unsigned long long r;
    asm("mov.b64 %0, {%1, %1};" : "=l"(r) : "f"(x));
    return r;
}
__device__ __forceinline__ void fma2(unsigned long long& d, unsigned long long a,
                                     unsigned long long b) {
    asm("fma.rn.f32x2 %0, %1, %2, %0;" : "+l"(d) : "l"(a), "l"(b));
}
__device__ __forceinline__ void mul2(unsigned long long& d, unsigned long long a) {
    asm("mul.rn.f32x2 %0, %0, %1;" : "+l"(d) : "l"(a));
}
__device__ __forceinline__ float2 unpack2(unsigned long long v) {
    float2 f;
    asm("mov.b64 {%0, %1}, %2;" : "=f"(f.x), "=f"(f.y) : "l"(v));
    return f;
}
__device__ __forceinline__ float ex2(float x) {
    float y;
    asm("ex2.approx.ftz.f32 %0, %1;" : "=f"(y) : "f"(x));
    return y;
}

// ---------------- bf16 split helpers -----------------------------------------
__device__ __forceinline__ unsigned short f2bf(float x) {
    unsigned short r;
    asm("cvt.rn.bf16.f32 %0, %1;" : "=h"(r) : "f"(x));
    return r;
}
__device__ __forceinline__ float bf2f(unsigned short h) {
    return __uint_as_float(((unsigned int)h) << 16);
}

// mma.m16n8k16 bf16, fp32 accumulate
__device__ __forceinline__ void mma16816(float* d, const unsigned* a, const unsigned* b) {
    asm volatile(
        "mma.sync.aligned.m16n8k16.row.col.f32.bf16.bf16.f32 "
        "{%0,%1,%2,%3}, {%4,%5,%6,%7}, {%8,%9}, {%0,%1,%2,%3};"
        : "+f"(d[0]), "+f"(d[1]), "+f"(d[2]), "+f"(d[3])
        : "r"(a[0]), "r"(a[1]), "r"(a[2]), "r"(a[3]), "r"(b[0]), "r"(b[1]));
}

// ---------------------------------------------------------------------------
// GEMM + bias via bf16 tensor cores with 2-way split (3 MMA passes):
//   x = hi + lo (bf16 each);  A@W ~= Ah@Wh + Ah@Wl + Al@Wh   (err ~ 2^-17)
// C[M,N] = A[M,K] @ W[K,N] + bias[N].  CTA tile 128x128, BK=16.
// 8 warps, each 32(M) x 64(N): 2 m16 frags x 8 n8 frags.
// A stored row-major [m][k] halves, B stored n-major [n][k] halves, so all
// fragment loads are plain 4-byte LDS (k-pairs contiguous). Pitch 18 halves.
// ---------------------------------------------------------------------------
__global__ __launch_bounds__(256)
void gemm_bf16split(const float* __restrict__ A, const float* __restrict__ W,
                    const float* __restrict__ bias, float* __restrict__ C,
                    int M, int N, int K) {
    constexpr int P = 18;  // smem pitch in halves (36B rows: 4B-aligned words)
    __shared__ unsigned short Ah[128 * P], Al[128 * P];
    __shared__ unsigned short Bh[128 * P], Bl[128 * P];

    const int tid = threadIdx.x;
    const int m0 = blockIdx.y * 128;
    const int n0 = blockIdx.x * 128;

    // --- loader mapping ---
    const int arow = tid >> 1, acol = (tid & 1) * 8;   // A tile 128x16 fp32
    const int krow = tid >> 4, ncol = (tid & 15) * 8;  // W tile 16x128 fp32
    const float* Ap = A + (size_t)(m0 + arow) * K + acol;
    const float* Wp = W + (size_t)krow * N + n0 + ncol;

    // --- warp/lane mapping ---
    const int wid = tid >> 5, lane = tid & 31;
    const int g = lane >> 2, t = lane & 3;
    const int wm = (wid & 3) * 32;   // warp M offset
    const int wn = (wid >> 2) * 64;  // warp N offset

    float acc[2][8][4];
#pragma unroll
    for (int mi = 0; mi < 2; mi++)
#pragma unroll
        for (int ni = 0; ni < 8; ni++)
#pragma unroll
            for (int r = 0; r < 4; r++) acc[mi][ni][r] = 0.f;

    float4 pa0 = *(const float4*)(Ap);
    float4 pa1 = *(const float4*)(Ap + 4);
    float4 pw0 = *(const float4*)(Wp);
    float4 pw1 = *(const float4*)(Wp + 4);

    for (int k0 = 0; k0 < K; k0 += 16) {
        __syncthreads();  // previous iteration's fragment reads complete
        // --- convert + store A slab (row-major) ---
        {
            float f[8] = {pa0.x, pa0.y, pa0.z, pa0.w, pa1.x, pa1.y, pa1.z, pa1.w};
#pragma unroll
            for (int i = 0; i < 8; i++) {
                unsigned short h = f2bf(f[i]);
                unsigned short l = f2bf(f[i] - bf2f(h));
                Ah[arow * P + acol + i] = h;
                Al[arow * P + acol + i] = l;
            }
        }
        // --- convert + store W slab (transposed to n-major) ---
        {
            float f[8] = {pw0.x, pw0.y, pw0.z, pw0.w, pw1.x, pw1.y, pw1.z, pw1.w};
#pragma unroll
            for (int i = 0; i < 8; i++) {
                unsigned short h = f2bf(f[i]);
                unsigned short l = f2bf(f[i] - bf2f(h));
                Bh[(ncol + i) * P + krow] = h;
                Bl[(ncol + i) * P + krow] = l;
            }
        }
        __syncthreads();
        if (k0 + 16 < K) {  // prefetch next slab while MMAs run
            pa0 = *(const float4*)(Ap + k0 + 16);
            pa1 = *(const float4*)(Ap + k0 + 20);
            pw0 = *(const float4*)(Wp + (size_t)(k0 + 16) * N);
            pw1 = *(const float4*)(Wp + (size_t)(k0 + 16) * N + 4);
        }

        // --- fragment loads ---
        unsigned ah[2][4], al[2][4], bh[8][2], bl[8][2];
#pragma unroll
        for (int mi = 0; mi < 2; mi++) {
            int r0 = (wm + mi * 16 + g) * P;
            int r8 = (wm + mi * 16 + 8 + g) * P;
            ah[mi][0] = *(const unsigned*)&Ah[r0 + 2 * t];
            ah[mi][1] = *(const unsigned*)&Ah[r8 + 2 * t];
            ah[mi][2] = *(const unsigned*)&Ah[r0 + 8 + 2 * t];
            ah[mi][3] = *(const unsigned*)&Ah[r8 + 8 + 2 * t];
            al[mi][0] = *(const unsigned*)&Al[r0 + 2 * t];
            al[mi][1] = *(const unsigned*)&Al[r8 + 2 * t];
            al[mi][2] = *(const unsigned*)&Al[r0 + 8 + 2 * t];
            al[mi][3] = *(const unsigned*)&Al[r8 + 8 + 2 * t];
        }
#pragma unroll
        for (int ni = 0; ni < 8; ni++) {
            int rn = (wn + ni * 8 + g) * P;
            bh[ni][0] = *(const unsigned*)&Bh[rn + 2 * t];
            bh[ni][1] = *(const unsigned*)&Bh[rn + 8 + 2 * t];
            bl[ni][0] = *(const unsigned*)&Bl[rn + 2 * t];
            bl[ni][1] = *(const unsigned*)&Bl[rn + 8 + 2 * t];
        }

        // --- 3 split passes ---
#pragma unroll
        for (int mi = 0; mi < 2; mi++)
#pragma unroll
            for (int ni = 0; ni < 8; ni++) mma16816(acc[mi][ni], ah[mi], bh[ni]);
#pragma unroll
        for (int mi = 0; mi < 2; mi++)
#pragma unroll
            for (int ni = 0; ni < 8; ni++) mma16816(acc[mi][ni], ah[mi], bl[ni]);
#pragma unroll
        for (int mi = 0; mi < 2; mi++)
#pragma unroll
            for (int ni = 0; ni < 8; ni++) mma16816(acc[mi][ni], al[mi], bh[ni]);
    }

    // --- epilogue: bias + store ---
#pragma unroll
    for (int mi = 0; mi < 2; mi++) {
        int row = m0 + wm + mi * 16 + g;
#pragma unroll
        for (int ni = 0; ni < 8; ni++) {
            int col = n0 + wn + ni * 8 + 2 * t;
            float b0 = bias[col], b1 = bias[col + 1];
            float2 v0 = make_float2(acc[mi][ni][0] + b0, acc[mi][ni][1] + b1);
            float2 v1 = make_float2(acc[mi][ni][2] + b0, acc[mi][ni][3] + b1);
            *(float2*)(C + (size_t)row * N + col) = v0;
            *(float2*)(C + (size_t)(row + 8) * N + col) = v1;
        }
    }
}

// ---------------------------------------------------------------------------
// Fused attention faithful to the reference (unchanged from R3 passing kernel):
//   p = softmax over ALL keys (full-row denominator)
//   out[q] = sum_{k<=q} p[q,k] V[k]  - 1e9 * sum_{k>q} V[k]
// ---------------------------------------------------------------------------
constexpr float SCALE_LOG2E = 0.08838834764831845f * 1.4426950408889634f;
constexpr int TP = 132;  // tile row pitch (floats)
constexpr size_t ATTN_SMEM = (size_t)(3 * 128 * TP + 256) * sizeof(float);

__global__ __launch_bounds__(256, 1)
void attn_kernel(const float* __restrict__ Q, const float* __restrict__ K,
                 const float* __restrict__ V, float* __restrict__ O) {
    extern __shared__ float sm[];
    float* Qs = sm;                     // Qs[q][d]  (pre-scaled by SCALE*log2e)
    float* B1 = sm + 128 * TP;          // Kt[d][k] during scores; P[q][k] after
    float* Vs = sm + 2 * 128 * TP;      // Vs[k][d]
    float* scr = sm + 3 * 128 * TP;     // 256 floats scratch (V colsum)

    const int tid = threadIdx.x;
    const int tx = tid & 15;
    const int ty = tid >> 4;
    const int qb = blockIdx.x;
    const int h = blockIdx.y;
    const int b = blockIdx.z;
    const int q0 = qb * 128;

    const float* Qg = Q + ((size_t)b * S + q0) * D + h * DH;
    const float* Kg = K + (size_t)b * S * D + h * DH;
    const float* Vg = V + (size_t)b * S * D + h * DH;

    {
        const int lane = tid & 31;
#pragma unroll
        for (int it = 0; it < 16; it++) {
            int row = it * 8 + (tid >> 5);
            float4 v = *(const float4*)(Qg + (size_t)row * D + lane * 4);
            v.x *= SCALE_LOG2E; v.y *= SCALE_LOG2E;
            v.z *= SCALE_LOG2E; v.w *= SCALE_LOG2E;
            *(float4*)&Qs[row * TP + lane * 4] = v;
        }
    }

    unsigned long long acc[8][4];
#pragma unroll
    for (int i = 0; i < 8; i++)
#pragma unroll
        for (int j = 0; j < 4; j++) acc[i][j] = 0ull;
    float m_r[8], l_r[8];
#pragma unroll
    for (int i = 0; i < 8; i++) { m_r[i] = -1e30f; l_r[i] = 0.f; }

    float psum = 0.f;
    const int cd = tid & 127;
    const int ck0 = (tid >> 7) * 64;

    constexpr int NT = S / 128;  // 16
    for (int tix = 0; tix < NT; tix++) {
        const int j = (tix < NT - 1) ? (tix < qb ? tix : tix + 1) : qb;  // diag LAST

        {
            const int r2 = tid >> 1, c2 = (tid & 1) * 64;
            const float* Kr = Kg + (size_t)(j * 128 + r2) * D + c2;
            const float* Vr = Vg + (size_t)(j * 128 + r2) * D + c2;
#pragma unroll
            for (int f = 0; f < 16; f++) {
                float4 kv = *(const float4*)(Kr + f * 4);
                B1[(c2 + f * 4 + 0) * TP + r2] = kv.x;
                B1[(c2 + f * 4 + 1) * TP + r2] = kv.y;
                B1[(c2 + f * 4 + 2) * TP + r2] = kv.z;
                B1[(c2 + f * 4 + 3) * TP + r2] = kv.w;
                *(float4*)&Vs[r2 * TP + c2 + f * 4] = *(const float4*)(Vr + f * 4);
            }
        }
        __syncthreads();

        unsigned long long sacc[8][4];
#pragma unroll
        for (int i = 0; i < 8; i++)
#pragma unroll
            for (int jp = 0; jp < 4; jp++) sacc[i][jp] = 0ull;

        for (int d0 = 0; d0 < 128; d0 += 2) {
            float2 qv[8];
#pragma unroll
            for (int i = 0; i < 8; i++)
                qv[i] = *(const float2*)&Qs[(ty * 8 + i) * TP + d0];
#pragma unroll
            for (int dd = 0; dd < 2; dd++) {
                ulonglong2 b0 = *(const ulonglong2*)&B1[(d0 + dd) * TP + tx * 4];
                ulonglong2 b1 = *(const ulonglong2*)&B1[(d0 + dd) * TP + 64 + tx * 4];
#pragma unroll
                for (int i = 0; i < 8; i++) {
                    unsigned long long ad = dup2(dd ? qv[i].y : qv[i].x);
                    fma2(sacc[i][0], ad, b0.x);
                    fma2(sacc[i][1], ad, b0.y);
                    fma2(sacc[i][2], ad, b1.x);
                    fma2(sacc[i][3], ad, b1.y);
                }
            }
        }

        float p[8][8];
#pragma unroll
        for (int i = 0; i < 8; i++) {
#pragma unroll
            for (int jp = 0; jp < 4; jp++) {
                float2 f = unpack2(sacc[i][jp]);
                p[i][2 * jp] = f.x;
                p[i][2 * jp + 1] = f.y;
            }
            float rm = p[i][0];
#pragma unroll
            for (int jj = 1; jj < 8; jj++) rm = fmaxf(rm, p[i][jj]);
            rm = fmaxf(rm, __shfl_xor_sync(0xffffffffu, rm, 1));
            rm = fmaxf(rm, __shfl_xor_sync(0xffffffffu, rm, 2));
            rm = fmaxf(rm, __shfl_xor_sync(0xffffffffu, rm, 4));
            rm = fmaxf(rm, __shfl_xor_sync(0xffffffffu, rm, 8));
            float mn = fmaxf(m_r[i], rm);
            float fac = ex2(m_r[i] - mn);
            m_r[i] = mn;
            float rs = 0.f;
#pragma unroll
            for (int jj = 0; jj < 8; jj++) {
                float e = ex2(p[i][jj] - mn);
                p[i][jj] = e;
                rs += e;
            }
            rs += __shfl_xor_sync(0xffffffffu, rs, 1);
            rs += __shfl_xor_sync(0xffffffffu, rs, 2);
            rs += __shfl_xor_sync(0xffffffffu, rs, 4);
            rs += __shfl_xor_sync(0xffffffffu, rs, 8);
            l_r[i] = l_r[i] * fac + rs;
            unsigned long long fd = dup2(fac);
#pragma unroll
            for (int jp = 0; jp < 4; jp++) mul2(acc[i][jp], fd);
        }

        if (j <= qb) {
            if (j == qb) {
#pragma unroll
                for (int i = 0; i < 8; i++)
#pragma unroll
                    for (int jj = 0; jj < 8; jj++) {
                        int col = (jj < 4) ? tx * 4 + jj : 64 + tx * 4 + jj - 4;
                        if (col > ty * 8 + i) p[i][jj] = 0.f;
                    }
            }
            __syncthreads();
#pragma unroll
            for (int i = 0; i < 8; i++) {
                *(float4*)&B1[(ty * 8 + i) * TP + tx * 4] =
                    make_float4(p[i][0], p[i][1], p[i][2], p[i][3]);
                *(float4*)&B1[(ty * 8 + i) * TP + 64 + tx * 4] =
                    make_float4(p[i][4], p[i][5], p[i][6], p[i][7]);
            }
            __syncthreads();
            for (int k0 = 0; k0 < 128; k0 += 2) {
                float2 pv[8];
#pragma unroll
                for (int i = 0; i < 8; i++)
                    pv[i] = *(const float2*)&B1[(ty * 8 + i) * TP + k0];
#pragma unroll
                for (int kk = 0; kk < 2; kk++) {
                    ulonglong2 b0 = *(const ulonglong2*)&Vs[(k0 + kk) * TP + tx * 4];
                    ulonglong2 b1 = *(const ulonglong2*)&Vs[(k0 + kk) * TP + 64 + tx * 4];
#pragma unroll
                    for (int i = 0; i < 8; i++) {
                        unsigned long long ad = dup2(kk ? pv[i].y : pv[i].x);
                        fma2(acc[i][0], ad, b0.x);
                        fma2(acc[i][1], ad, b0.y);
                        fma2(acc[i][2], ad, b1.x);
                        fma2(acc[i][3], ad, b1.y);
                    }
                }
            }
        } else {
            for (int k = ck0; k < ck0 + 64; k++) psum += Vs[k * TP + cd];
        }
        __syncthreads();
    }

    scr[tid] = psum;
    __syncthreads();
    if (tid < 128) scr[tid] += scr[tid + 128];
    __syncthreads();

    float inv_l[8];
#pragma unroll
    for (int i = 0; i < 8; i++) inv_l[i] = 1.f / l_r[i];
    float sfv[8];
#pragma unroll
    for (int jj = 0; jj < 8; jj++) {
        int col = (jj < 4) ? tx * 4 + jj : 64 + tx * 4 + jj - 4;
        sfv[jj] = scr[col];
    }

    const int qlo = ty * 8;
    float run[8];
#pragma unroll
    for (int jj = 0; jj < 8; jj++) run[jj] = 0.f;

    float* Obase = O + ((size_t)b * S + q0) * D + h * DH;
    int kk = 127;
#pragma unroll
    for (int i = 7; i >= 0; --i) {
        const int q = qlo + i;
        for (; kk > q; --kk) {
            float4 v0 = *(const float4*)&Vs[kk * TP + tx * 4];
            float4 v1 = *(const float4*)&Vs[kk * TP + 64 + tx * 4];
            run[0] += v0.x; run[1] += v0.y; run[2] += v0.z; run[3] += v0.w;
            run[4] += v1.x; run[5] += v1.y; run[6] += v1.z; run[7] += v1.w;
        }
        float o[8];
#pragma unroll
        for (int jp = 0; jp < 4; jp++) {
            float2 f = unpack2(acc[i][jp]);
            o[2 * jp] = f.x;
            o[2 * jp + 1] = f.y;
        }
#pragma unroll
        for (int jj = 0; jj < 8; jj++)
            o[jj] = o[jj] * inv_l[i] - 1e9f * (sfv[jj] + run[jj]);
        float* Op = Obase + (size_t)q * D;
        *(float4*)(Op + tx * 4) = make_float4(o[0], o[1], o[2], o[3]);
        *(float4*)(Op + 64 + tx * 4) = make_float4(o[4], o[5], o[6], o[7]);
    }
}

// ---------------------------------------------------------------------------
extern "C" void kernel_launch(void* const* d_in, const int* in_sizes, int n_in,
                              void* d_out, int out_size) {
    const float* q  = (const float*)d_in[0];
    const float* k  = (const float*)d_in[1];
    const float* v  = (const float*)d_in[2];
    const float* Wq = (const float*)d_in[3];
    const float* bq = (const float*)d_in[4];
    const float* Wk = (const float*)d_in[5];
    const float* bk = (const float*)d_in[6];
    const float* Wv = (const float*)d_in[7];
    const float* bv = (const float*)d_in[8];
    const float* Wo = (const float*)d_in[9];
    const float* bo = (const float*)d_in[10];
    float* out = (float*)d_out;

    float *Qb, *Kb, *Vb, *Ab;
    cudaGetSymbolAddress((void**)&Qb, g_Q);
    cudaGetSymbolAddress((void**)&Kb, g_K);
    cudaGetSymbolAddress((void**)&Vb, g_V);
    cudaGetSymbolAddress((void**)&Ab, g_A);

    cudaFuncSetAttribute(attn_kernel, cudaFuncAttributeMaxDynamicSharedMemorySize,
                         (int)ATTN_SMEM);

    dim3 gg(D / 128, M_ROWS / 128);  // (16, 64)
    gemm_bf16split<<<gg, 256>>>(q, Wq, bq, Qb, M_ROWS, D, D);
    gemm_bf16split<<<gg, 256>>>(k, Wk, bk, Kb, M_ROWS, D, D);
    gemm_bf16split<<<gg, 256>>>(v, Wv, bv, Vb, M_ROWS, D, D);

    attn_kernel<<<dim3(S / 128, H, Bc), 256, ATTN_SMEM>>>(Qb, Kb, Vb, Ab);

    gemm_bf16split<<<gg, 256>>>(Ab, Wo, bo, out, M_ROWS, D, D);
}